// round 4
// baseline (speedup 1.0000x reference)
#include <cuda_runtime.h>
#include <math.h>
#include <stdint.h>

// ---- static configuration ----
#define NXI 256
#define NYI 256
#define NS  128
// sigma in mm: TIME_RES*0.3/2/2.355 = 300*0.3/2/2.355
#define SIGMA_MM 19.10828025477707f
#define WIN_NSIG 4.5f
// FILT_C = (pi * tof_sigma_pix)^2 ; tof_sigma_pix = SIGMA_MM / DX
#define FILT_C ((float)(9.554140127388535 * 3.14159265358979323846 * \
                        9.554140127388535 * 3.14159265358979323846))

// ---- scratch buffers (device globals: no allocation allowed) ----
__device__ float  g_img[NYI * NXI];
__device__ float2 g_bufA[NYI * NXI];

// ================= zero the accumulator image =================
__global__ void zero_img_kernel() {
    int i = blockIdx.x * blockDim.x + threadIdx.x;   // 16384 threads, float4
    ((float4*)g_img)[i] = make_float4(0.f, 0.f, 0.f, 0.f);
}

// ================= TOF backprojection =================
// One warp per event; the +-4.5 sigma window (<=29 samples) fits one warp pass.
__global__ void bp_kernel(const float* __restrict__ proj,
                          const float* __restrict__ tof,
                          const float* __restrict__ x1l, const float* __restrict__ y1l,
                          const float* __restrict__ x1r, const float* __restrict__ y1r,
                          const float* __restrict__ x2l, const float* __restrict__ y2l,
                          const float* __restrict__ x2r, const float* __restrict__ y2r,
                          int E) {
    int e    = blockIdx.x * (blockDim.x >> 5) + (threadIdx.x >> 5);
    int lane = threadIdx.x & 31;
    if (e >= E) return;

    const float X1 = 0.5f * (x1l[e] + x1r[e]);
    const float Y1 = 0.5f * (y1l[e] + y1r[e]);
    const float X2 = 0.5f * (x2l[e] + x2r[e]);
    const float Y2 = 0.5f * (y2l[e] + y2r[e]);
    const float ddx = X2 - X1, ddy = Y2 - Y1;
    const float L = sqrtf(ddx * ddx + ddy * ddy);
    const float center = 0.5f * L + tof[e] * 0.15f;       // tof*0.3/2
    const float amp = proj[e] * L * (1.0f / (float)NS);   // proj * L/NS
    const float inv_sigma = 1.0f / SIGMA_MM;
    const float invL = 1.0f / L;

    // sample window: |z| <= 4.5 sigma
    const float tlo = (center - WIN_NSIG * SIGMA_MM) * invL;
    const float thi = (center + WIN_NSIG * SIGMA_MM) * invL;
    int klo = (int)ceilf(tlo * (float)NS - 0.5f);
    int khi = (int)floorf(thi * (float)NS - 0.5f);
    if (klo < 0) klo = 0;
    if (khi > NS - 1) khi = NS - 1;

    // window width <= 29 samples -> this loop runs at most once per lane
    for (int k = klo + lane; k <= khi; k += 32) {
        float t = ((float)k + 0.5f) * (1.0f / (float)NS);   // exact
        float z = (t * L - center) * inv_sigma;
        // match reference (unfused mul+add) on the index path
        float px = __fadd_rn(X1, __fmul_rn(t, ddx));
        float py = __fadd_rn(Y1, __fmul_rn(t, ddy));
        int ix = (int)floorf(__fadd_rn(__fmul_rn(px, 0.5f), 128.0f));
        int iy = (int)floorf(__fadd_rn(__fmul_rn(py, 0.5f), 128.0f));
        if ((unsigned)ix < 256u && (unsigned)iy < 256u) {
            float w = __expf(-0.5f * z * z) * amp;
            atomicAdd(&g_img[iy * NXI + ix], w);
        }
    }
}

// ================= shared-memory radix-2 FFT, N=256 =================
// 128 threads per block; twiddle table in shared memory.
__device__ __forceinline__ int brev8(int i) {
    return (int)(__brev((unsigned)i) >> 24);
}

// tw[m] = (cos(-pi*m/128), sin(-pi*m/128)); inverse uses conjugate.
__device__ __forceinline__ void make_twiddles(float2* tw, int tid) {
    if (tid < 128) {
        float ang = -3.14159265358979323846f * (float)tid * (1.0f / 128.0f);
        float sn, cs;
        sincosf(ang, &sn, &cs);
        tw[tid] = make_float2(cs, sn);
    }
}

template <int INV>
__device__ __forceinline__ void fft256(float2* sm, const float2* tw, int tid) {
    #pragma unroll
    for (int stage = 0; stage < 8; ++stage) {
        int half = 1 << stage;
        __syncthreads();
        int j = tid & (half - 1);
        int base = ((tid & ~(half - 1)) << 1) + j;
        int m = j << (7 - stage);
        float cs = tw[m].x;
        float sn = INV ? -tw[m].y : tw[m].y;
        float2 a = sm[base];
        float2 b = sm[base + half];
        float tr = b.x * cs - b.y * sn;
        float ti = b.x * sn + b.y * cs;
        sm[base]        = make_float2(a.x + tr, a.y + ti);
        sm[base + half] = make_float2(a.x - tr, a.y - ti);
    }
    __syncthreads();
}

// forward FFT over rows; input: g_img / 4 (the /DX/DY normalization)
__global__ void fft_rows_fwd_kernel() {
    __shared__ float2 s[256];
    __shared__ float2 tw[128];
    int y = blockIdx.x, tid = threadIdx.x;
    make_twiddles(tw, tid);
    s[brev8(tid)]       = make_float2(g_img[y * NXI + tid] * 0.25f, 0.0f);
    s[brev8(tid + 128)] = make_float2(g_img[y * NXI + tid + 128] * 0.25f, 0.0f);
    fft256<0>(s, tw, tid);
    g_bufA[y * NXI + tid]       = s[tid];
    g_bufA[y * NXI + tid + 128] = s[tid + 128];
}

// i0e(x) = exp(-x) * I0(x), Abramowitz-Stegun 9.8.1 / 9.8.2 (rel err ~2e-7)
__device__ __forceinline__ float i0e_f(float x) {
    if (x < 3.75f) {
        float t = x * (1.0f / 3.75f);
        t *= t;
        float I0 = 1.0f + t * (3.5156229f + t * (3.0899424f + t * (1.2067492f +
                   t * (0.2659732f + t * (0.0360768f + t * 0.0045813f)))));
        return I0 * expf(-x);
    } else {
        float t = 3.75f / x;
        float p = 0.39894228f + t * (0.01328592f + t * (0.00225319f +
                  t * (-0.00157565f + t * (0.00916281f + t * (-0.02057706f +
                  t * (0.02635537f + t * (-0.01647633f + t * 0.00392377f)))))));
        return p * rsqrtf(x);
    }
}

// shifted-grid frequency coordinate for FFT index k
__device__ __forceinline__ float ufreq(int k) {
    float u = ((float)k + 0.5f) * (1.0f / 128.0f);
    return (k < 128) ? u : (u - 2.0f);
}

// fused: forward FFT over cols + filter (incl. 1/256 scale) + inverse FFT over cols
__global__ void fft_cols_fused_kernel() {
    __shared__ float2 s[256];
    __shared__ float2 s2[256];
    __shared__ float2 tw[128];
    int x = blockIdx.x, tid = threadIdx.x;
    make_twiddles(tw, tid);
    s[brev8(tid)]       = g_bufA[tid * NXI + x];
    s[brev8(tid + 128)] = g_bufA[(tid + 128) * NXI + x];
    fft256<0>(s, tw, tid);

    float ux = ufreq(x);
    float cx = ux * ux;
    #pragma unroll
    for (int r = tid; r < 256; r += 128) {
        float uy = ufreq(r);
        float tmp = FILT_C * (uy * uy + cx);
        float f = (1.0f / 256.0f) / i0e_f(tmp);
        float2 v = s[r];
        s2[brev8(r)] = make_float2(v.x * f, v.y * f);
    }
    // fft256 starts with __syncthreads -> s2 writes are visible
    fft256<1>(s2, tw, tid);
    g_bufA[tid * NXI + x]         = s2[tid];
    g_bufA[(tid + 128) * NXI + x] = s2[tid + 128];
}

// inverse FFT over rows, write real part to output
__global__ void fft_rows_inv_kernel(float* __restrict__ out) {
    __shared__ float2 s[256];
    __shared__ float2 tw[128];
    int y = blockIdx.x, tid = threadIdx.x;
    make_twiddles(tw, tid);
    s[brev8(tid)]       = g_bufA[y * NXI + tid];
    s[brev8(tid + 128)] = g_bufA[y * NXI + tid + 128];
    fft256<1>(s, tw, tid);
    out[y * NXI + tid]       = s[tid].x;
    out[y * NXI + tid + 128] = s[tid + 128].x;
}

extern "C" void kernel_launch(void* const* d_in, const int* in_sizes, int n_in,
                              void* d_out, int out_size) {
    const float* proj = (const float*)d_in[0];
    const float* tof  = (const float*)d_in[1];
    const float* x1l  = (const float*)d_in[2];
    const float* y1l  = (const float*)d_in[3];
    const float* x1r  = (const float*)d_in[4];
    const float* y1r  = (const float*)d_in[5];
    const float* x2l  = (const float*)d_in[6];
    const float* y2l  = (const float*)d_in[7];
    const float* x2r  = (const float*)d_in[8];
    const float* y2r  = (const float*)d_in[9];
    int E = in_sizes[0];

    zero_img_kernel<<<16, 1024>>>();   // 16384 threads x float4 = 65536 floats

    int warpsPerBlock = 8;
    int blocks = (E + warpsPerBlock - 1) / warpsPerBlock;
    bp_kernel<<<blocks, warpsPerBlock * 32>>>(proj, tof, x1l, y1l, x1r, y1r,
                                              x2l, y2l, x2r, y2r, E);

    fft_rows_fwd_kernel<<<256, 128>>>();
    fft_cols_fused_kernel<<<256, 128>>>();
    fft_rows_inv_kernel<<<256, 128>>>((float*)d_out);
}

// round 6
// speedup vs baseline: 1.6957x; 1.6957x over previous
#include <cuda_runtime.h>
#include <math.h>
#include <stdint.h>

// ---- static configuration ----
#define NXI 256
#define NYI 256
#define NS  128
#define NREP 8           // image replicas to spread atomic contention
// sigma in mm: TIME_RES*0.3/2/2.355 = 300*0.3/2/2.355
#define SIGMA_MM 19.10828025477707f
#define WIN_NSIG 4.5f
// FILT_C = (pi * tof_sigma_pix)^2 ; tof_sigma_pix = SIGMA_MM / DX
#define FILT_C ((float)(9.554140127388535 * 3.14159265358979323846 * \
                        9.554140127388535 * 3.14159265358979323846))

// ---- scratch buffers (device globals: no allocation allowed) ----
__device__ float  g_imgR[NREP * NYI * NXI];   // 2 MB, L2-resident
__device__ float2 g_bufA[NYI * NXI];

// ================= zero the replicated accumulator =================
__global__ void zero_img_kernel() {
    int i = blockIdx.x * blockDim.x + threadIdx.x;   // 131072 float4 slots
    ((float4*)g_imgR)[i] = make_float4(0.f, 0.f, 0.f, 0.f);
}

// e^{-y} for y in [0, ~10.5], FMA/ALU pipes only (no MUFU).
// |rel err| ~ 1.5e-7.
__device__ __forceinline__ float expneg(float y) {
    float nf = rintf(y * 1.4426950408889634f);
    float f  = fmaf(nf, -0.6931471805599453f, y);    // f in [-0.347, 0.347]
    float g  = -f;
    float p  = fmaf(g, 0.0013888889f, 0.008333334f);
    p = fmaf(g, p, 0.041666668f);
    p = fmaf(g, p, 0.16666667f);
    p = fmaf(g, p, 0.5f);
    p = fmaf(g, p, 1.0f);
    p = fmaf(g, p, 1.0f);                            // e^{-f}
    float s = __int_as_float((127 - (int)nf) << 23); // 2^{-n}
    return p * s;
}

// ================= TOF backprojection =================
// One warp per event; the +-4.5 sigma window (<=29 samples) fits one warp pass.
__global__ void bp_kernel(const float* __restrict__ proj,
                          const float* __restrict__ tof,
                          const float* __restrict__ x1l, const float* __restrict__ y1l,
                          const float* __restrict__ x1r, const float* __restrict__ y1r,
                          const float* __restrict__ x2l, const float* __restrict__ y2l,
                          const float* __restrict__ x2r, const float* __restrict__ y2r,
                          int E) {
    int e    = blockIdx.x * (blockDim.x >> 5) + (threadIdx.x >> 5);
    int lane = threadIdx.x & 31;
    if (e >= E) return;
    float* img = g_imgR + ((blockIdx.x & (NREP - 1)) << 16);

    const float X1 = 0.5f * (x1l[e] + x1r[e]);
    const float Y1 = 0.5f * (y1l[e] + y1r[e]);
    const float X2 = 0.5f * (x2l[e] + x2r[e]);
    const float Y2 = 0.5f * (y2l[e] + y2r[e]);
    const float ddx = X2 - X1, ddy = Y2 - Y1;
    const float L = sqrtf(ddx * ddx + ddy * ddy);
    const float center = 0.5f * L + tof[e] * 0.15f;       // tof*0.3/2
    const float amp = proj[e] * L * (1.0f / (float)NS);   // proj * L/NS
    const float inv_sigma = 1.0f / SIGMA_MM;
    const float invL = 1.0f / L;

    // sample window: |z| <= 4.5 sigma
    const float tlo = (center - WIN_NSIG * SIGMA_MM) * invL;
    const float thi = (center + WIN_NSIG * SIGMA_MM) * invL;
    int klo = (int)ceilf(tlo * (float)NS - 0.5f);
    int khi = (int)floorf(thi * (float)NS - 0.5f);
    if (klo < 0) klo = 0;
    if (khi > NS - 1) khi = NS - 1;

    // window width <= 29 samples -> at most one iteration per lane
    for (int k = klo + lane; k <= khi; k += 32) {
        float t = ((float)k + 0.5f) * (1.0f / (float)NS);   // exact
        float z = (t * L - center) * inv_sigma;
        // match reference (unfused mul+add) on the index path
        float px = __fadd_rn(X1, __fmul_rn(t, ddx));
        float py = __fadd_rn(Y1, __fmul_rn(t, ddy));
        int ix = (int)floorf(__fadd_rn(__fmul_rn(px, 0.5f), 128.0f));
        int iy = (int)floorf(__fadd_rn(__fmul_rn(py, 0.5f), 128.0f));
        if ((unsigned)ix < 256u && (unsigned)iy < 256u) {
            float w = expneg(0.5f * z * z) * amp;
            atomicAdd(&img[iy * NXI + ix], w);
        }
    }
}

// ================= shared-memory radix-2 FFT, N=256 =================
__device__ __forceinline__ int brev8(int i) {
    return (int)(__brev((unsigned)i) >> 24);
}

// tw[m] = (cos(-pi*m/128), sin(-pi*m/128)); inverse uses conjugate.
__device__ __forceinline__ void make_twiddles(float2* tw, int tid) {
    if (tid < 128) {
        float ang = -3.14159265358979323846f * (float)tid * (1.0f / 128.0f);
        float sn, cs;
        sincosf(ang, &sn, &cs);
        tw[tid] = make_float2(cs, sn);
    }
}

template <int INV>
__device__ __forceinline__ void fft256(float2* sm, const float2* tw, int tid) {
    #pragma unroll
    for (int stage = 0; stage < 8; ++stage) {
        int half = 1 << stage;
        __syncthreads();
        int j = tid & (half - 1);
        int base = ((tid & ~(half - 1)) << 1) + j;
        int m = j << (7 - stage);
        float cs = tw[m].x;
        float sn = INV ? -tw[m].y : tw[m].y;
        float2 a = sm[base];
        float2 b = sm[base + half];
        float tr = b.x * cs - b.y * sn;
        float ti = b.x * sn + b.y * cs;
        sm[base]        = make_float2(a.x + tr, a.y + ti);
        sm[base + half] = make_float2(a.x - tr, a.y - ti);
    }
    __syncthreads();
}

// replica-reduce + forward FFT over rows; scale by 1/4 (the /DX/DY norm)
__global__ void fft_rows_fwd_kernel() {
    __shared__ float2 s[256];
    __shared__ float2 tw[128];
    int y = blockIdx.x, tid = threadIdx.x;
    make_twiddles(tw, tid);
    #pragma unroll
    for (int h = 0; h < 2; ++h) {
        int p = y * NXI + tid + h * 128;
        float v = 0.0f;
        #pragma unroll
        for (int r = 0; r < NREP; ++r) v += g_imgR[(r << 16) + p];
        s[brev8(tid + h * 128)] = make_float2(v * 0.25f, 0.0f);
    }
    fft256<0>(s, tw, tid);
    g_bufA[y * NXI + tid]       = s[tid];
    g_bufA[y * NXI + tid + 128] = s[tid + 128];
}

// i0e(x) = exp(-x) * I0(x), Abramowitz-Stegun 9.8.1 / 9.8.2 (rel err ~2e-7)
__device__ __forceinline__ float i0e_f(float x) {
    if (x < 3.75f) {
        float t = x * (1.0f / 3.75f);
        t *= t;
        float I0 = 1.0f + t * (3.5156229f + t * (3.0899424f + t * (1.2067492f +
                   t * (0.2659732f + t * (0.0360768f + t * 0.0045813f)))));
        return I0 * expf(-x);
    } else {
        float t = 3.75f / x;
        float p = 0.39894228f + t * (0.01328592f + t * (0.00225319f +
                  t * (-0.00157565f + t * (0.00916281f + t * (-0.02057706f +
                  t * (0.02635537f + t * (-0.01647633f + t * 0.00392377f)))))));
        return p * rsqrtf(x);
    }
}

// shifted-grid frequency coordinate for FFT index k
__device__ __forceinline__ float ufreq(int k) {
    float u = ((float)k + 0.5f) * (1.0f / 128.0f);
    return (k < 128) ? u : (u - 2.0f);
}

// fused: forward FFT over cols + filter (incl. 1/256 scale) + inverse FFT over cols
__global__ void fft_cols_fused_kernel() {
    __shared__ float2 s[256];
    __shared__ float2 s2[256];
    __shared__ float2 tw[128];
    int x = blockIdx.x, tid = threadIdx.x;
    make_twiddles(tw, tid);
    s[brev8(tid)]       = g_bufA[tid * NXI + x];
    s[brev8(tid + 128)] = g_bufA[(tid + 128) * NXI + x];
    fft256<0>(s, tw, tid);

    float ux = ufreq(x);
    float cx = ux * ux;
    #pragma unroll
    for (int r = tid; r < 256; r += 128) {
        float uy = ufreq(r);
        float tmp = FILT_C * (uy * uy + cx);
        float f = (1.0f / 256.0f) / i0e_f(tmp);
        float2 v = s[r];
        s2[brev8(r)] = make_float2(v.x * f, v.y * f);
    }
    // fft256 starts with __syncthreads -> s2 writes are visible
    fft256<1>(s2, tw, tid);
    g_bufA[tid * NXI + x]         = s2[tid];
    g_bufA[(tid + 128) * NXI + x] = s2[tid + 128];
}

// inverse FFT over rows, write real part to output
__global__ void fft_rows_inv_kernel(float* __restrict__ out) {
    __shared__ float2 s[256];
    __shared__ float2 tw[128];
    int y = blockIdx.x, tid = threadIdx.x;
    make_twiddles(tw, tid);
    s[brev8(tid)]       = g_bufA[y * NXI + tid];
    s[brev8(tid + 128)] = g_bufA[y * NXI + tid + 128];
    fft256<1>(s, tw, tid);
    out[y * NXI + tid]       = s[tid].x;
    out[y * NXI + tid + 128] = s[tid + 128].x;
}

extern "C" void kernel_launch(void* const* d_in, const int* in_sizes, int n_in,
                              void* d_out, int out_size) {
    const float* proj = (const float*)d_in[0];
    const float* tof  = (const float*)d_in[1];
    const float* x1l  = (const float*)d_in[2];
    const float* y1l  = (const float*)d_in[3];
    const float* x1r  = (const float*)d_in[4];
    const float* y1r  = (const float*)d_in[5];
    const float* x2l  = (const float*)d_in[6];
    const float* y2l  = (const float*)d_in[7];
    const float* x2r  = (const float*)d_in[8];
    const float* y2r  = (const float*)d_in[9];
    int E = in_sizes[0];

    zero_img_kernel<<<128, 1024>>>();   // NREP * 65536 floats / 4 per thread

    int warpsPerBlock = 8;
    int blocks = (E + warpsPerBlock - 1) / warpsPerBlock;
    bp_kernel<<<blocks, warpsPerBlock * 32>>>(proj, tof, x1l, y1l, x1r, y1r,
                                              x2l, y2l, x2r, y2r, E);

    fft_rows_fwd_kernel<<<256, 128>>>();
    fft_cols_fused_kernel<<<256, 128>>>();
    fft_rows_inv_kernel<<<256, 128>>>((float*)d_out);
}

// round 11
// speedup vs baseline: 1.8134x; 1.0694x over previous
#include <cuda_runtime.h>
#include <math.h>
#include <stdint.h>

// ---- static configuration ----
#define NXI 256
#define NYI 256
#define NS  128
#define NREP 8           // image replicas to spread atomic contention
// sigma in mm: TIME_RES*0.3/2/2.355 = 300*0.3/2/2.355
#define SIGMA_MM 19.10828025477707f
#define WIN_NSIG 4.0f
// FILT_C = (pi * tof_sigma_pix)^2 ; tof_sigma_pix = SIGMA_MM / DX
#define FILT_C ((float)(9.554140127388535 * 3.14159265358979323846 * \
                        9.554140127388535 * 3.14159265358979323846))

// ---- scratch buffers (device globals: no allocation allowed) ----
__device__ float  g_imgR[NREP * NYI * NXI];   // 2 MB, L2-resident
__device__ float2 g_bufA[NYI * NXI];
__device__ float2 g_tw[128];                  // twiddle table (precomputed once)

// ====== zero the replicated accumulator + precompute twiddles ======
__global__ void zero_img_kernel() {
    int i = blockIdx.x * blockDim.x + threadIdx.x;   // 131072 float4 slots
    ((float4*)g_imgR)[i] = make_float4(0.f, 0.f, 0.f, 0.f);
    if (blockIdx.x == 0 && threadIdx.x < 128) {
        float ang = -3.14159265358979323846f * (float)threadIdx.x * (1.0f / 128.0f);
        float sn, cs;
        sincosf(ang, &sn, &cs);
        g_tw[threadIdx.x] = make_float2(cs, sn);
    }
}

// e^{-y} for y in [0, ~10.5], FMA/ALU pipes only (no MUFU).
// |rel err| ~ 1.5e-7.
__device__ __forceinline__ float expneg(float y) {
    float nf = rintf(y * 1.4426950408889634f);
    float f  = fmaf(nf, -0.6931471805599453f, y);    // f in [-0.347, 0.347]
    float g  = -f;
    float p  = fmaf(g, 0.0013888889f, 0.008333334f);
    p = fmaf(g, p, 0.041666668f);
    p = fmaf(g, p, 0.16666667f);
    p = fmaf(g, p, 0.5f);
    p = fmaf(g, p, 1.0f);
    p = fmaf(g, p, 1.0f);                            // e^{-f}
    float s = __int_as_float((127 - (int)nf) << 23); // 2^{-n}
    return p * s;
}

// ================= TOF backprojection =================
// One warp per event; the +-4 sigma window (<=26 samples) fits one warp pass.
__global__ void bp_kernel(const float* __restrict__ proj,
                          const float* __restrict__ tof,
                          const float* __restrict__ x1l, const float* __restrict__ y1l,
                          const float* __restrict__ x1r, const float* __restrict__ y1r,
                          const float* __restrict__ x2l, const float* __restrict__ y2l,
                          const float* __restrict__ x2r, const float* __restrict__ y2r,
                          int E) {
    int e    = blockIdx.x * (blockDim.x >> 5) + (threadIdx.x >> 5);
    int lane = threadIdx.x & 31;
    if (e >= E) return;
    float* img = g_imgR + ((blockIdx.x & (NREP - 1)) << 16);

    const float X1 = 0.5f * (x1l[e] + x1r[e]);
    const float Y1 = 0.5f * (y1l[e] + y1r[e]);
    const float X2 = 0.5f * (x2l[e] + x2r[e]);
    const float Y2 = 0.5f * (y2l[e] + y2r[e]);
    const float ddx = X2 - X1, ddy = Y2 - Y1;
    const float L = sqrtf(ddx * ddx + ddy * ddy);
    const float center = 0.5f * L + tof[e] * 0.15f;       // tof*0.3/2
    const float amp = proj[e] * L * (1.0f / (float)NS);   // proj * L/NS
    const float inv_sigma = 1.0f / SIGMA_MM;
    const float invL = 1.0f / L;

    // sample window: |z| <= 4 sigma
    const float tlo = (center - WIN_NSIG * SIGMA_MM) * invL;
    const float thi = (center + WIN_NSIG * SIGMA_MM) * invL;
    int klo = (int)ceilf(tlo * (float)NS - 0.5f);
    int khi = (int)floorf(thi * (float)NS - 0.5f);
    if (klo < 0) klo = 0;
    if (khi > NS - 1) khi = NS - 1;

    // window width <= 26 samples -> at most one iteration per lane
    for (int k = klo + lane; k <= khi; k += 32) {
        float t = ((float)k + 0.5f) * (1.0f / (float)NS);   // exact
        float z = (t * L - center) * inv_sigma;
        // match reference (unfused mul+add) on the index path
        float px = __fadd_rn(X1, __fmul_rn(t, ddx));
        float py = __fadd_rn(Y1, __fmul_rn(t, ddy));
        int ix = (int)floorf(__fadd_rn(__fmul_rn(px, 0.5f), 128.0f));
        int iy = (int)floorf(__fadd_rn(__fmul_rn(py, 0.5f), 128.0f));
        if ((unsigned)ix < 256u && (unsigned)iy < 256u) {
            float w = expneg(0.5f * z * z) * amp;
            atomicAdd(&img[iy * NXI + ix], w);
        }
    }
}

// ================= shared-memory radix-2 FFT, N=256 =================
__device__ __forceinline__ int brev8(int i) {
    return (int)(__brev((unsigned)i) >> 24);
}

template <int INV>
__device__ __forceinline__ void fft256(float2* sm, const float2* tw, int tid) {
    #pragma unroll
    for (int stage = 0; stage < 8; ++stage) {
        int half = 1 << stage;
        __syncthreads();
        int j = tid & (half - 1);
        int base = ((tid & ~(half - 1)) << 1) + j;
        int m = j << (7 - stage);
        float cs = tw[m].x;
        float sn = INV ? -tw[m].y : tw[m].y;
        float2 a = sm[base];
        float2 b = sm[base + half];
        float tr = b.x * cs - b.y * sn;
        float ti = b.x * sn + b.y * cs;
        sm[base]        = make_float2(a.x + tr, a.y + ti);
        sm[base + half] = make_float2(a.x - tr, a.y - ti);
    }
    __syncthreads();
}

// replica-reduce + forward FFT over rows; scale by 1/4 (the /DX/DY norm)
__global__ void fft_rows_fwd_kernel() {
    __shared__ float2 s[256];
    __shared__ float2 tw[128];
    int y = blockIdx.x, tid = threadIdx.x;
    tw[tid] = g_tw[tid];
    #pragma unroll
    for (int h = 0; h < 2; ++h) {
        int p = y * NXI + tid + h * 128;
        float v = 0.0f;
        #pragma unroll
        for (int r = 0; r < NREP; ++r) v += g_imgR[(r << 16) + p];
        s[brev8(tid + h * 128)] = make_float2(v * 0.25f, 0.0f);
    }
    fft256<0>(s, tw, tid);   // leading __syncthreads covers tw/s writes
    g_bufA[y * NXI + tid]       = s[tid];
    g_bufA[y * NXI + tid + 128] = s[tid + 128];
}

// i0e(x) = exp(-x) * I0(x), Abramowitz-Stegun 9.8.1 / 9.8.2 (rel err ~2e-7)
__device__ __forceinline__ float i0e_f(float x) {
    if (x < 3.75f) {
        float t = x * (1.0f / 3.75f);
        t *= t;
        float I0 = 1.0f + t * (3.5156229f + t * (3.0899424f + t * (1.2067492f +
                   t * (0.2659732f + t * (0.0360768f + t * 0.0045813f)))));
        return I0 * expf(-x);
    } else {
        float t = 3.75f / x;
        float p = 0.39894228f + t * (0.01328592f + t * (0.00225319f +
                  t * (-0.00157565f + t * (0.00916281f + t * (-0.02057706f +
                  t * (0.02635537f + t * (-0.01647633f + t * 0.00392377f)))))));
        return p * rsqrtf(x);
    }
}

// shifted-grid frequency coordinate for FFT index k
__device__ __forceinline__ float ufreq(int k) {
    float u = ((float)k + 0.5f) * (1.0f / 128.0f);
    return (k < 128) ? u : (u - 2.0f);
}

// fused: forward FFT over cols + filter (incl. 1/256 scale) + inverse FFT over cols
__global__ void fft_cols_fused_kernel() {
    __shared__ float2 s[256];
    __shared__ float2 s2[256];
    __shared__ float2 tw[128];
    int x = blockIdx.x, tid = threadIdx.x;
    tw[tid] = g_tw[tid];
    s[brev8(tid)]       = g_bufA[tid * NXI + x];
    s[brev8(tid + 128)] = g_bufA[(tid + 128) * NXI + x];
    fft256<0>(s, tw, tid);

    float ux = ufreq(x);
    float cx = ux * ux;
    #pragma unroll
    for (int r = tid; r < 256; r += 128) {
        float uy = ufreq(r);
        float tmp = FILT_C * (uy * uy + cx);
        float f = (1.0f / 256.0f) / i0e_f(tmp);
        float2 v = s[r];
        s2[brev8(r)] = make_float2(v.x * f, v.y * f);
    }
    // fft256 starts with __syncthreads -> s2 writes are visible
    fft256<1>(s2, tw, tid);
    g_bufA[tid * NXI + x]         = s2[tid];
    g_bufA[(tid + 128) * NXI + x] = s2[tid + 128];
}

// inverse FFT over rows, write real part to output
__global__ void fft_rows_inv_kernel(float* __restrict__ out) {
    __shared__ float2 s[256];
    __shared__ float2 tw[128];
    int y = blockIdx.x, tid = threadIdx.x;
    tw[tid] = g_tw[tid];
    s[brev8(tid)]       = g_bufA[y * NXI + tid];
    s[brev8(tid + 128)] = g_bufA[y * NXI + tid + 128];
    fft256<1>(s, tw, tid);
    out[y * NXI + tid]       = s[tid].x;
    out[y * NXI + tid + 128] = s[tid + 128].x;
}

extern "C" void kernel_launch(void* const* d_in, const int* in_sizes, int n_in,
                              void* d_out, int out_size) {
    const float* proj = (const float*)d_in[0];
    const float* tof  = (const float*)d_in[1];
    const float* x1l  = (const float*)d_in[2];
    const float* y1l  = (const float*)d_in[3];
    const float* x1r  = (const float*)d_in[4];
    const float* y1r  = (const float*)d_in[5];
    const float* x2l  = (const float*)d_in[6];
    const float* y2l  = (const float*)d_in[7];
    const float* x2r  = (const float*)d_in[8];
    const float* y2r  = (const float*)d_in[9];
    int E = in_sizes[0];

    zero_img_kernel<<<128, 1024>>>();   // NREP * 65536 floats / 4 per thread

    int warpsPerBlock = 8;
    int blocks = (E + warpsPerBlock - 1) / warpsPerBlock;
    bp_kernel<<<blocks, warpsPerBlock * 32>>>(proj, tof, x1l, y1l, x1r, y1r,
                                              x2l, y2l, x2r, y2r, E);

    fft_rows_fwd_kernel<<<256, 128>>>();
    fft_cols_fused_kernel<<<256, 128>>>();
    fft_rows_inv_kernel<<<256, 128>>>((float*)d_out);
}